// round 12
// baseline (speedup 1.0000x reference)
#include <cuda_runtime.h>
#include <math.h>

#define Nn 8
#define Tt 64
#define Aa 65536
#define Cc 80
#define NFLT4 (Aa * (Cc / 4))          // float4s of y_pred per image
#define ITER 8
#define SBX_PER_N 640
#define SBX (SBX_PER_N * Nn)            // 5120 stream blocks
#define K1B ((Aa / 256) * Nn)           // 2048 assignment blocks
#define TOTB (SBX + K1B)

#define F_EPS 1e-6f
#define SL1_BETA (1.0f / 9.0f)
#define LN2 0.69314718055994531f
#define OVR_FLAG 0x40000000

// ---------------- scratch ----------------
__device__ int            g_state[Nn * Aa];
__device__ int            g_asg[Nn * Aa];
__device__ int            g_nvalid[Nn];
__device__ unsigned char  g_vt[Nn * Tt];
__device__ unsigned char  g_label[Nn * Tt];
__device__ unsigned long long g_gtkey[Nn * Tt];
__device__ int            g_poscnt[Nn];
__device__ float          g_pcls[SBX];
__device__ float          g_acls[K1B];
__device__ float          g_abox[K1B];
__device__ float          g_dcls;
__device__ float          g_dbox;
__device__ unsigned       g_done1;

// ---------------- helpers ----------------
__device__ __forceinline__ float rcp_approx(float x) {
    float r; asm("rcp.approx.f32 %0, %1;" : "=f"(r) : "f"(x)); return r;
}
__device__ __forceinline__ float ex2a(float x) {
    float r; asm("ex2.approx.f32 %0, %1;" : "=f"(r) : "f"(x)); return r;
}
__device__ __forceinline__ float lg2a(float x) {
    float r; asm("lg2.approx.f32 %0, %1;" : "=f"(r) : "f"(x)); return r;
}
__device__ __forceinline__ float slctf(float a, float b, float c) {
    float r; asm("slct.f32.f32 %0, %1, %2, %3;" : "=f"(r) : "f"(a), "f"(b), "f"(c)); return r;
}

__device__ __forceinline__ float focal_A(float l) {       // 3 MUFU
    float t  = ex2a(fabsf(l) * -1.44269504f);
    float u  = 1.0f + t;
    float r  = rcp_approx(u);
    float w  = r * r;
    float tr = t * r;
    float v  = tr * tr;
    float p2 = slctf(w, v, l);
    float ce = fmaf(lg2a(u), (float)LN2, fmaxf(l, 0.f));
    return p2 * ce;
}
__device__ __forceinline__ float focal_B(float l) {       // 2 MUFU
    float t  = ex2a(fabsf(l) * -1.44269504f);
    float u  = 1.0f + t;
    float x  = fmaf(2.0f, u, -3.0f);
    float r  = fmaf(-0.028572f, x, 0.08326f);
    r = fmaf(r, x, -0.22121f);
    r = fmaf(r, x, 0.66548f);
    r = r * fmaf(-u, r, 2.0f);
    float w  = r * r;
    float tr = t * r;
    float v  = tr * tr;
    float p2 = slctf(w, v, l);
    float ce = fmaf(lg2a(u), (float)LN2, fmaxf(l, 0.f));
    return p2 * ce;
}
__device__ __forceinline__ float focal4mix(float4 vv) {
    return focal_A(vv.x) + focal_B(vv.y) + focal_A(vv.z) + focal_B(vv.w);
}

// label-element correction: + a*q^2*sp(-l) - (1-a)*p^2*sp(l)
__device__ __forceinline__ float pos_cls_corr(float lsel) {
    float mm = fabsf(lsel);
    float em = __expf(-mm);
    float uu = 1.0f + em;
    float r  = rcp_approx(uu);
    float lgv = __logf(uu);
    float p  = (lsel >= 0.f) ? r : em * r;
    float qd = 1.0f - p;
    float ce  = lgv + fmaxf(lsel, 0.f);
    float cep = lgv + fmaxf(-lsel, 0.f);
    return 0.25f * qd * qd * cep - 0.75f * p * p * ce;
}

__device__ __forceinline__ float box_loss(float4 an, float4 bp, float4 bt) {
    float wa = fmaxf(an.z - an.x, F_EPS);
    float ha = fmaxf(an.w - an.y, F_EPS);
    float cxa = an.x + 0.5f * wa;
    float cya = an.y + 0.5f * ha;
    float wt = fmaxf(bt.z - bt.x, F_EPS);
    float ht = fmaxf(bt.w - bt.y, F_EPS);
    float cxt = bt.x + 0.5f * (bt.z - bt.x);
    float cyt = bt.y + 0.5f * (bt.w - bt.y);
    float tg0 = (cxt - cxa) / wa;
    float tg1 = (cyt - cya) / ha;
    float tg2 = logf(wt / wa);
    float tg3 = logf(ht / ha);
    float d0 = fabsf(tg0 - bp.x), d1 = fabsf(tg1 - bp.y);
    float d2 = fabsf(tg2 - bp.z), d3 = fabsf(tg3 - bp.w);
    float s = 0.f;
    s += (d0 < SL1_BETA) ? (0.5f * d0 * d0 / SL1_BETA) : (d0 - 0.5f * SL1_BETA);
    s += (d1 < SL1_BETA) ? (0.5f * d1 * d1 / SL1_BETA) : (d1 - 0.5f * SL1_BETA);
    s += (d2 < SL1_BETA) ? (0.5f * d2 * d2 / SL1_BETA) : (d2 - 0.5f * SL1_BETA);
    s += (d3 < SL1_BETA) ? (0.5f * d3 * d3 / SL1_BETA) : (d3 - 0.5f * SL1_BETA);
    return s;
}

// ---------------- Launch A ----------------
__global__ void __launch_bounds__(256, 4)
kA(const float4* __restrict__ anchors,
   const float4* __restrict__ bb,
   const float* __restrict__ y_true,
   const float4* __restrict__ yp4,
   const float4* __restrict__ bbp4) {
    int bid = blockIdx.x;
    int tid = threadIdx.x;

    if (bid >= K1B) {
        // ===== streaming focal (R9-proven mixed-pipe loop) =====
        int sb = bid - K1B;
        int n = sb / SBX_PER_N;
        int bx = sb - n * SBX_PER_N;
        const float4* yp = yp4 + (size_t)n * NFLT4 + bx * (256 * ITER);
        float acc0 = 0.f, acc1 = 0.f;
        #pragma unroll
        for (int i = 0; i < ITER; i++) {
            float4 vv = yp[i * 256 + tid];
            acc0 += focal_A(vv.x) + focal_A(vv.z);
            acc1 += focal_B(vv.y) + focal_B(vv.w);
        }
        float clsl = acc0 + acc1;
        unsigned full = 0xFFFFFFFFu;
        #pragma unroll
        for (int o = 16; o > 0; o >>= 1)
            clsl += __shfl_down_sync(full, clsl, o);
        __shared__ float wc[8];
        int w = tid >> 5, lane = tid & 31;
        if (lane == 0) wc[w] = clsl;
        __syncthreads();
        if (tid == 0) {
            float c = 0.f;
            #pragma unroll
            for (int i = 0; i < 8; i++) c += wc[i];
            g_pcls[sb] = 0.75f * c;
        }
        return;
    }

    // ===== assignment + in-block corrections =====
    int n = bid >> 8;
    int axb = bid & 255;
    const float4* yp_n = yp4 + (size_t)n * NFLT4;

    __shared__ float4 sbox[Tt];          // compacted valid boxes
    __shared__ float4 sraw[Tt];          // raw rows by t (for box corr)
    __shared__ float  sarea[Tt];
    __shared__ unsigned char svt[Tt];
    __shared__ int    slab[Tt];          // labels by t
    __shared__ unsigned long long swkey[8][Tt];
    __shared__ unsigned smask[2];
    __shared__ int snv, cI, cP;
    __shared__ int ligns[256], lpos[256];

    float4 myb; bool myvalid = false; unsigned mk = 0;
    if (tid < 64) {
        myb = bb[n * Tt + tid];
        sraw[tid] = myb;
        myvalid = (myb.x > 0.f) || (myb.y > 0.f) || (myb.z > 0.f) || (myb.w > 0.f);
        mk = __ballot_sync(0xFFFFFFFFu, myvalid);
        if ((tid & 31) == 0) smask[tid >> 5] = mk;
    }
    if (tid >= 64 && tid < 128) {        // labels (shared; axb==0 also global)
        int t = tid - 64;
        const float4* row = (const float4*)(y_true + (size_t)(n * Tt + t) * Cc);
        int lab = 0;
        #pragma unroll 4
        for (int qq = 0; qq < Cc / 4; qq++) {
            float4 v = row[qq];
            if (v.x > 0.5f) lab = 4 * qq;
            if (v.y > 0.5f) lab = 4 * qq + 1;
            if (v.z > 0.5f) lab = 4 * qq + 2;
            if (v.w > 0.5f) lab = 4 * qq + 3;
        }
        slab[t] = lab;
        if (axb == 0) g_label[n * Tt + t] = (unsigned char)lab;
    }
    if (tid == 0) { cI = 0; cP = 0; }
    __syncthreads();
    if (tid < 64 && myvalid) {
        int pos = __popc(mk & ((1u << (tid & 31)) - 1)) +
                  ((tid >= 32) ? __popc(smask[0]) : 0);
        sbox[pos]  = myb;
        sarea[pos] = fmaxf(myb.z - myb.x, 0.f) * fmaxf(myb.w - myb.y, 0.f);
        svt[pos]   = (unsigned char)tid;
        if (axb == 0) g_vt[n * Tt + pos] = (unsigned char)tid;
    }
    if (tid == 0) {
        snv = __popc(smask[0]) + __popc(smask[1]);
        if (axb == 0) g_nvalid[n] = snv;
    }
    __syncthreads();
    int nv = snv;

    int a = axb * 256 + tid;
    float4 an = anchors[a];
    float a2 = fmaxf(an.z - an.x, 0.f) * fmaxf(an.w - an.y, 0.f);
    unsigned lane = tid & 31;
    int w = tid >> 5;

    float best = -1.0f; int arg = 0;
    for (int k = 0; k < nv; k++) {
        float4 b = sbox[k];
        float lx = fmaxf(b.x, an.x), ly = fmaxf(b.y, an.y);
        float rx = fminf(b.z, an.z), ry = fminf(b.w, an.w);
        float iw = fmaxf(rx - lx, 0.f), ih = fmaxf(ry - ly, 0.f);
        float inter = iw * ih;
        float uni = sarea[k] + a2 - inter;
        float iou = inter / fmaxf(uni, 1e-10f);       // exact div
        if (iou > best) { best = iou; arg = svt[k]; } // first-max (smallest t)

        unsigned ib = __float_as_uint(iou);
        unsigned mx = __reduce_max_sync(0xFFFFFFFFu, ib);
        unsigned msk = __ballot_sync(0xFFFFFFFFu, ib == mx);
        if (lane == (unsigned)(__ffs(msk) - 1))
            swkey[w][k] = ((unsigned long long)mx << 32) |
                          (unsigned long long)(~(unsigned)a);
    }
    __syncthreads();

    int idx = n * Aa + a;
    int st = (best >= 0.5f) ? 2 : ((best < 0.4f) ? 1 : 0);
    g_asg[idx]   = arg;
    g_state[idx] = st;

    // pos count (warp-aggregated) + local work lists
    {
        unsigned bpos = __ballot_sync(0xFFFFFFFFu, st == 2);
        if (lane == 0 && bpos) atomicAdd(&g_poscnt[n], __popc(bpos));
    }
    if (st == 0) { int s = atomicAdd(&cI, 1); ligns[s] = tid; }
    if (st == 2) { int s = atomicAdd(&cP, 1); lpos[s] = tid; }

    if (tid < nv) {
        unsigned long long m = swkey[0][tid];
        #pragma unroll
        for (int ww = 1; ww < 8; ww++) {
            unsigned long long o = swkey[ww][tid];
            if (o > m) m = o;
        }
        if ((m >> 32) != 0)
            atomicMax(&g_gtkey[n * Tt + tid], m);
    }
    __syncthreads();

    // ----- in-block corrections (overlap with stream blocks) -----
    float clsc = 0.f, boxc = 0.f;
    int base_a = axb * 256;
    int nItems = cI * 20;
    for (int it = tid; it < nItems; it += 256) {
        int e = it / 20, qq = it - e * 20;
        int aa = base_a + ligns[e];
        float4 vv = yp_n[(size_t)aa * 20 + qq];
        clsc = fmaf(-0.75f, focal4mix(vv), clsc);
    }
    for (int e = tid; e < cP; e += 256) {
        int alocal = lpos[e];
        int aa = base_a + alocal;
        int asgp = g_asg[n * Aa + aa];        // own block's write (pre-override)
        int lab = slab[asgp];
        float4 vv = yp_n[(size_t)aa * 20 + (lab >> 2)];
        int j = lab & 3;
        float lsel = (j == 0) ? vv.x : ((j == 1) ? vv.y : ((j == 2) ? vv.z : vv.w));
        clsc += pos_cls_corr(lsel);
        boxc += box_loss(anchors[aa], bbp4[n * Aa + aa], sraw[asgp]);
    }
    // block reduce corrections
    {
        unsigned full = 0xFFFFFFFFu;
        #pragma unroll
        for (int o = 16; o > 0; o >>= 1) {
            clsc += __shfl_down_sync(full, clsc, o);
            boxc += __shfl_down_sync(full, boxc, o);
        }
        __shared__ float wcc[8], wbb[8];
        if (lane == 0) { wcc[w] = clsc; wbb[w] = boxc; }
        __syncthreads();
        if (tid == 0) {
            float c = 0.f, b = 0.f;
            #pragma unroll
            for (int i = 0; i < 8; i++) { c += wcc[i]; b += wbb[i]; }
            g_acls[bid] = c;
            g_abox[bid] = b;
        }
    }

    // ----- LQ override tail (last finishing assignment block) -----
    __syncthreads();
    __threadfence();
    __shared__ bool slast;
    if (tid == 0)
        slast = (atomicAdd(&g_done1, 1u) == (unsigned)(K1B - 1));
    __syncthreads();
    if (!slast) return;

    __shared__ int sP[Nn * Tt];
    __shared__ int sOldV[Nn * Tt];
    __shared__ signed char sOldSt[Nn * Tt];
    __shared__ signed char sT[Nn * Tt];

    // pass 1: apply overrides, record originals
    for (int idx2 = tid; idx2 < Nn * Tt; idx2 += 256) {
        sP[idx2] = -1;
        int nn = idx2 >> 6, k = idx2 & 63;
        if (k < g_nvalid[nn]) {
            unsigned long long key = g_gtkey[nn * Tt + k];
            if ((key >> 32) != 0) {
                int aa = (int)(~(unsigned)(key & 0xFFFFFFFFull));
                int t = g_vt[nn * Tt + k];
                int p = nn * Aa + aa;
                int oldv  = atomicMax(&g_asg[p], OVR_FLAG | t);
                int oldst = atomicExch(&g_state[p], 2);
                sP[idx2] = p; sOldV[idx2] = oldv;
                sOldSt[idx2] = (signed char)oldst; sT[idx2] = (signed char)t;
            }
        }
    }
    __syncthreads();

    // pass 2: winner applies delta corrections
    float clsd = 0.f, boxd = 0.f;
    for (int idx2 = tid; idx2 < Nn * Tt; idx2 += 256) {
        int p = sP[idx2];
        if (p < 0) continue;
        int finalv = g_asg[p];
        int t_final = finalv & 63;
        if ((int)sT[idx2] != t_final) continue;        // unique winner per anchor
        // recover original state and assignment
        int orig_state = 2, orig_asg = -1;
        for (int jj = 0; jj < Nn * Tt; jj++) {
            if (sP[jj] == p) {
                if (sOldSt[jj] != 2) orig_state = sOldSt[jj];
                if (!(sOldV[jj] & OVR_FLAG)) orig_asg = sOldV[jj];
            }
        }
        int nn = p >> 16;
        int aa = p & (Aa - 1);
        const float4* yp = yp4 + (size_t)nn * NFLT4 + (size_t)aa * 20;

        if (orig_state != 2) atomicAdd(&g_poscnt[nn], 1);
        if (orig_state == 0) {                         // was ignore: re-add focal sum
            float S = 0.f;
            #pragma unroll 4
            for (int qq = 0; qq < 20; qq++) S += focal4mix(yp[qq]);
            clsd = fmaf(0.75f, S, clsd);
        }
        if (orig_state == 2) {                         // subtract stale pos correction
            int lab = (int)g_label[nn * Tt + orig_asg];
            float4 vv = yp[lab >> 2];
            int j = lab & 3;
            float lsel = (j == 0) ? vv.x : ((j == 1) ? vv.y : ((j == 2) ? vv.z : vv.w));
            clsd -= pos_cls_corr(lsel);
            float4 btold = bb[nn * Tt + orig_asg];
            boxd -= box_loss(anchors[aa], bbp4[p], btold);
        }
        // add new pos correction with final assignment
        {
            int lab = (int)g_label[nn * Tt + t_final];
            float4 vv = yp[lab >> 2];
            int j = lab & 3;
            float lsel = (j == 0) ? vv.x : ((j == 1) ? vv.y : ((j == 2) ? vv.z : vv.w));
            clsd += pos_cls_corr(lsel);
            float4 btnew = bb[nn * Tt + t_final];
            boxd += box_loss(anchors[aa], bbp4[p], btnew);
        }
    }
    // reduce tail deltas
    {
        unsigned full = 0xFFFFFFFFu;
        #pragma unroll
        for (int o = 16; o > 0; o >>= 1) {
            clsd += __shfl_down_sync(full, clsd, o);
            boxd += __shfl_down_sync(full, boxd, o);
        }
        __shared__ float wcd[8], wbd[8];
        if (lane == 0) { wcd[w] = clsd; wbd[w] = boxd; }
        __syncthreads();
        if (tid == 0) {
            float c = 0.f, b = 0.f;
            #pragma unroll
            for (int i = 0; i < 8; i++) { c += wcd[i]; b += wbd[i]; }
            g_dcls = c;
            g_dbox = b;
        }
    }
}

// ---------------- Launch F: final reduce + output + resets ----------------
__global__ void __launch_bounds__(256)
kF(float* __restrict__ out) {
    __shared__ double sc[256], sb2[256];
    int tid = threadIdx.x;
    double c = 0.0, b = 0.0;
    for (int i = tid; i < SBX; i += 256) c += (double)g_pcls[i];
    for (int i = tid; i < K1B; i += 256) { c += (double)g_acls[i]; b += (double)g_abox[i]; }
    if (tid == 0) { c += (double)g_dcls; b += (double)g_dbox; }
    sc[tid] = c; sb2[tid] = b;
    __syncthreads();
    for (int s = 128; s > 0; s >>= 1) {
        if (tid < s) { sc[tid] += sc[tid + s]; sb2[tid] += sb2[tid + s]; }
        __syncthreads();
    }
    if (tid == 0) {
        double avg = 0.0;
        for (int nn = 0; nn < Nn; nn++) {
            double p = (double)g_poscnt[nn];
            avg += (p > 1.0) ? p : 1.0;
        }
        float clsO = (float)(sc[0] / avg);
        float boxO = (float)(sb2[0] / avg);
        if (isnan(clsO) || isinf(clsO)) clsO = 0.f;
        if (isnan(boxO) || isinf(boxO)) boxO = 0.f;
        out[0] = clsO;
        out[1] = boxO;
    }
    // resets for next graph replay
    __syncthreads();
    if (tid == 0) g_done1 = 0;
    if (tid < Nn) g_poscnt[tid] = 0;
    for (int i = tid; i < Nn * Tt; i += 256) g_gtkey[i] = 0ull;
}

// ---------------- launch ----------------
extern "C" void kernel_launch(void* const* d_in, const int* in_sizes, int n_in,
                              void* d_out, int out_size) {
    const float*  y_true    = (const float*)d_in[0];
    const float*  bbox_true = (const float*)d_in[1];
    const float*  y_pred    = (const float*)d_in[2];
    const float4* bbox_pred = (const float4*)d_in[3];
    const float4* anchors   = (const float4*)d_in[4];
    float* out = (float*)d_out;

    kA<<<TOTB, 256>>>(anchors, (const float4*)bbox_true, y_true,
                      (const float4*)y_pred, bbox_pred);
    kF<<<1, 256>>>(out);
}

// round 13
// speedup vs baseline: 1.6017x; 1.6017x over previous
#include <cuda_runtime.h>
#include <math.h>

#define Nn 8
#define Tt 64
#define Aa 65536
#define Cc 80
#define NFLT4 (Aa * (Cc / 4))          // float4s of y_pred per image = 1,310,720
#define ITER 8
#define SBX_PER_N 640                   // stream blocks per image
#define SBX (SBX_PER_N * Nn)            // 5120
#define K1B ((Aa / 256) * Nn)           // 2048
#define TOTB (SBX + K1B)                // 7168
#define QB 2048                         // correction blocks

#define F_EPS 1e-6f
#define SL1_BETA (1.0f / 9.0f)
#define LN2 0.69314718055994531f
#define IGN_FLAG (1 << 30)

// ---------------- scratch (device globals; no allocation) ----------------
__device__ int            g_state[Nn * Aa];   // 0=ignore 1=neg 2=pos
__device__ int            g_asg[Nn * Aa];     // bit30 = override, low bits = gt index t
__device__ int            g_nvalid[Nn];
__device__ unsigned char  g_vt[Nn * Tt];
__device__ unsigned char  g_label[Nn * Tt];
__device__ unsigned long long g_gtkey[Nn * Tt];
__device__ int            g_poscnt[Nn];
__device__ __align__(16) float g_pcls[SBX];
__device__ __align__(16) float g_qcls[QB];
__device__ __align__(16) float g_qbox[QB];
__device__ int            g_ignlist[Nn * Aa];
__device__ int            g_poslist[Nn * Aa];
__device__ int            g_nign;
__device__ int            g_npos;
__device__ unsigned       g_done1;
__device__ unsigned       g_doneB;

// ---------------- helpers ----------------
__device__ __forceinline__ float rcp_approx(float x) {
    float r; asm("rcp.approx.f32 %0, %1;" : "=f"(r) : "f"(x)); return r;
}
__device__ __forceinline__ float ex2a(float x) {
    float r; asm("ex2.approx.f32 %0, %1;" : "=f"(r) : "f"(x)); return r;
}
__device__ __forceinline__ float lg2a(float x) {
    float r; asm("lg2.approx.f32 %0, %1;" : "=f"(r) : "f"(x)); return r;
}
__device__ __forceinline__ float slctf(float a, float b, float c) {
    float r; asm("slct.f32.f32 %0, %1, %2, %3;" : "=f"(r) : "f"(a), "f"(b), "f"(c)); return r;
}

// Variant A: 3 MUFU (EX2, RCP, LG2)
__device__ __forceinline__ float focal_A(float l) {
    float t  = ex2a(fabsf(l) * -1.44269504f);   // e^{-|l|}
    float u  = 1.0f + t;
    float r  = rcp_approx(u);
    float w  = r * r;
    float tr = t * r;
    float v  = tr * tr;
    float p2 = slctf(w, v, l);                   // p^2
    float ce = fmaf(lg2a(u), (float)LN2, fmaxf(l, 0.f)); // softplus(l)
    return p2 * ce;
}

// Variant B: 2 MUFU (EX2, LG2), reciprocal on FMA pipe
__device__ __forceinline__ float focal_B(float l) {
    float t  = ex2a(fabsf(l) * -1.44269504f);
    float u  = 1.0f + t;
    float x  = fmaf(2.0f, u, -3.0f);
    float r  = fmaf(-0.028572f, x, 0.08326f);
    r = fmaf(r, x, -0.22121f);
    r = fmaf(r, x, 0.66548f);
    r = r * fmaf(-u, r, 2.0f);                   // Newton: rel err ~2e-6
    float w  = r * r;
    float tr = t * r;
    float v  = tr * tr;
    float p2 = slctf(w, v, l);
    float ce = fmaf(lg2a(u), (float)LN2, fmaxf(l, 0.f));
    return p2 * ce;
}

// ---------------- Launch A: assignment blocks first, then stream focal ----------------
__global__ void __launch_bounds__(256, 4)
kA(const float4* __restrict__ anchors,
   const float4* __restrict__ bb,
   const float* __restrict__ y_true,
   const float4* __restrict__ yp4) {
    int bid = blockIdx.x;
    int tid = threadIdx.x;

    if (bid >= K1B) {
        // ===== pure streaming focal; mixed-pipe variants, dual accumulators =====
        int sb = bid - K1B;
        int n = sb / SBX_PER_N;
        int bx = sb - n * SBX_PER_N;
        const float4* yp = yp4 + (size_t)n * NFLT4 + bx * (256 * ITER);
        float acc0 = 0.f, acc1 = 0.f;
        #pragma unroll
        for (int i = 0; i < ITER; i++) {
            float4 vv = yp[i * 256 + tid];
            acc0 += focal_A(vv.x) + focal_A(vv.z);
            acc1 += focal_B(vv.y) + focal_B(vv.w);
        }
        float clsl = acc0 + acc1;
        unsigned full = 0xFFFFFFFFu;
        #pragma unroll
        for (int o = 16; o > 0; o >>= 1)
            clsl += __shfl_down_sync(full, clsl, o);
        __shared__ float wc[8];
        int w = tid >> 5, lane = tid & 31;
        if (lane == 0) wc[w] = clsl;
        __syncthreads();
        if (tid == 0) {
            float c = 0.f;
            #pragma unroll
            for (int i = 0; i < 8; i++) c += wc[i];
            g_pcls[sb] = 0.75f * c;
        }
        return;
    }

    // ===== assignment =====
    int q = bid;
    int n = q >> 8;
    int axb = q & 255;

    __shared__ float4 sbox[Tt];
    __shared__ float  sarea[Tt];
    __shared__ unsigned char svt[Tt];
    __shared__ unsigned long long swkey[8][Tt];
    __shared__ unsigned smask[2];
    __shared__ int snv;

    float4 myb; bool myvalid = false; unsigned mk = 0;
    if (tid < 64) {
        myb = bb[n * Tt + tid];
        myvalid = (myb.x > 0.f) || (myb.y > 0.f) || (myb.z > 0.f) || (myb.w > 0.f);
        mk = __ballot_sync(0xFFFFFFFFu, myvalid);
        if ((tid & 31) == 0) smask[tid >> 5] = mk;
    }
    if (axb == 0 && tid >= 64 && tid < 128) {
        int r = n * Tt + (tid - 64);
        const float4* row = (const float4*)(y_true + (size_t)r * Cc);
        int lab = 0;
        #pragma unroll 4
        for (int qq = 0; qq < Cc / 4; qq++) {
            float4 v = row[qq];
            if (v.x > 0.5f) lab = 4 * qq;
            if (v.y > 0.5f) lab = 4 * qq + 1;
            if (v.z > 0.5f) lab = 4 * qq + 2;
            if (v.w > 0.5f) lab = 4 * qq + 3;
        }
        g_label[r] = (unsigned char)lab;
    }
    __syncthreads();
    if (tid < 64 && myvalid) {
        int pos = __popc(mk & ((1u << (tid & 31)) - 1)) +
                  ((tid >= 32) ? __popc(smask[0]) : 0);
        sbox[pos]  = myb;
        sarea[pos] = fmaxf(myb.z - myb.x, 0.f) * fmaxf(myb.w - myb.y, 0.f);
        svt[pos]   = (unsigned char)tid;
        if (axb == 0) g_vt[n * Tt + pos] = (unsigned char)tid;
    }
    if (tid == 0) {
        snv = __popc(smask[0]) + __popc(smask[1]);
        if (axb == 0) g_nvalid[n] = snv;
    }
    __syncthreads();
    int nv = snv;

    int a = axb * 256 + tid;
    float4 an = anchors[a];
    float a2 = fmaxf(an.z - an.x, 0.f) * fmaxf(an.w - an.y, 0.f);
    unsigned lane = tid & 31;
    int w = tid >> 5;

    float best = -1.0f; int arg = 0;
    for (int k = 0; k < nv; k++) {
        float4 b = sbox[k];
        float lx = fmaxf(b.x, an.x), ly = fmaxf(b.y, an.y);
        float rx = fminf(b.z, an.z), ry = fminf(b.w, an.w);
        float iw = fmaxf(rx - lx, 0.f), ih = fmaxf(ry - ly, 0.f);
        float inter = iw * ih;
        float uni = sarea[k] + a2 - inter;
        float iou = __fdividef(inter, fmaxf(uni, 1e-10f));  // approx div: ~2^-22 rel err
        if (iou > best) { best = iou; arg = svt[k]; }       // first-max (smallest t)

        unsigned ib = __float_as_uint(iou);
        unsigned mx = __reduce_max_sync(0xFFFFFFFFu, ib);
        unsigned msk = __ballot_sync(0xFFFFFFFFu, ib == mx);
        if (lane == (unsigned)(__ffs(msk) - 1))
            swkey[w][k] = ((unsigned long long)mx << 32) |
                          (unsigned long long)(~(unsigned)a);
    }
    __syncthreads();

    int idx = n * Aa + a;
    int st = (best >= 0.5f) ? 2 : ((best < 0.4f) ? 1 : 0);
    g_asg[idx]   = arg;
    g_state[idx] = st;

    // warp-aggregated list appends
    {
        unsigned bpos = __ballot_sync(0xFFFFFFFFu, st == 2);
        unsigned bign = __ballot_sync(0xFFFFFFFFu, st == 0);
        unsigned lmask = (1u << lane) - 1u;
        int basep = 0, basei = 0;
        if (lane == 0) {
            if (bpos) {
                basep = atomicAdd(&g_npos, __popc(bpos));
                atomicAdd(&g_poscnt[n], __popc(bpos));
            }
            if (bign) basei = atomicAdd(&g_nign, __popc(bign));
        }
        basep = __shfl_sync(0xFFFFFFFFu, basep, 0);
        basei = __shfl_sync(0xFFFFFFFFu, basei, 0);
        if (st == 2) g_poslist[basep + __popc(bpos & lmask)] = idx;
        if (st == 0) g_ignlist[basei + __popc(bign & lmask)] = idx;
    }

    if (tid < nv) {
        unsigned long long m = swkey[0][tid];
        #pragma unroll
        for (int ww = 1; ww < 8; ww++) {
            unsigned long long o = swkey[ww][tid];
            if (o > m) m = o;
        }
        if ((m >> 32) != 0)
            atomicMax(&g_gtkey[n * Tt + tid], m);
    }

    // fused low-quality override: last finishing assignment block applies all
    __syncthreads();
    __threadfence();
    __shared__ bool slast;
    if (tid == 0)
        slast = (atomicAdd(&g_done1, 1u) == (unsigned)(K1B - 1));
    __syncthreads();
    if (slast) {
        for (int idx2 = tid; idx2 < Nn * Tt; idx2 += 256) {
            int nn = idx2 >> 6, k = idx2 & 63;
            if (k < g_nvalid[nn]) {
                unsigned long long key = g_gtkey[nn * Tt + k];
                if ((key >> 32) != 0) {
                    int aa = (int)(~(unsigned)(key & 0xFFFFFFFFull));
                    int t = g_vt[nn * Tt + k];
                    int p = nn * Aa + aa;
                    atomicMax(&g_asg[p], 0x40000000 | t);
                    int old = atomicExch(&g_state[p], 2);
                    if (old != 2) {
                        int pp = atomicAdd(&g_npos, 1);
                        g_poslist[pp] = p | ((old == 0) ? IGN_FLAG : 0);
                        atomicAdd(&g_poscnt[nn], 1);
                    }
                }
            }
        }
    }
}

// ---------------- Launch B: list-driven corrections + finalize ----------------
__global__ void __launch_bounds__(256)
kB(const float4* __restrict__ yp4,
   const float4* __restrict__ anchors,
   const float4* __restrict__ bbp4,
   const float* __restrict__ bbox_true,
   float* __restrict__ out) {
    float cls = 0.f, box = 0.f;
    int gtid = blockIdx.x * 256 + threadIdx.x;
    const int stride = QB * 256;

    // ---- ignore subtraction: item = (entry, float4-q); 2-deep chain ----
    int nI = g_nign;
    int nItems = nI * 20;
    #pragma unroll 4
    for (int it = gtid; it < nItems; it += stride) {
        int e = it / 20;
        int qq = it - e * 20;
        int idx = g_ignlist[e];
        int n = idx >> 16;
        int a = idx & (Aa - 1);
        float4 vv = yp4[(size_t)n * NFLT4 + (size_t)a * 20 + qq];
        float S = focal_A(vv.x) + focal_B(vv.y) + focal_A(vv.z) + focal_B(vv.w);
        cls = fmaf(-0.75f, S, cls);
    }

    // ---- positive corrections: one work item = one pos anchor ----
    int nP = g_npos;
    for (int e = gtid; e < nP; e += stride) {
        int ent = g_poslist[e];
        int idx = ent & ~IGN_FLAG;
        int n = idx >> 16;
        int a = idx & (Aa - 1);
        const float4* yp = yp4 + (size_t)n * NFLT4 + (size_t)a * 20;

        if (ent & IGN_FLAG) {
            // was on the ignore list; its focal sum was subtracted above -> add back
            float S = 0.f;
            #pragma unroll 4
            for (int qq = 0; qq < 20; qq++) {
                float4 vv = yp[qq];
                S += focal_A(vv.x) + focal_B(vv.y) + focal_A(vv.z) + focal_B(vv.w);
            }
            cls = fmaf(0.75f, S, cls);
        }

        int v = g_asg[idx];
        int asg = (v & 0x40000000) ? (v & 0xFF) : v;
        int label = (int)g_label[n * Tt + asg];
        float4 vv = yp[label >> 2];
        int j = label & 3;
        float lsel = (j == 0) ? vv.x : ((j == 1) ? vv.y : ((j == 2) ? vv.z : vv.w));
        {
            float mm = fabsf(lsel);
            float em = __expf(-mm);
            float uu = 1.0f + em;
            float r  = rcp_approx(uu);
            float lgv = __logf(uu);
            float p  = (lsel >= 0.f) ? r : em * r;
            float qd = 1.0f - p;
            float ce  = lgv + fmaxf(lsel, 0.f);
            float cep = lgv + fmaxf(-lsel, 0.f);
            cls += 0.25f * qd * qd * cep - 0.75f * p * p * ce;
        }
        float4 an = anchors[a];
        float4 bp = bbp4[idx];
        const float* bt = bbox_true + ((size_t)n * Tt + asg) * 4;
        float bx1 = bt[0], by1 = bt[1], bx2 = bt[2], by2 = bt[3];
        float wa = fmaxf(an.z - an.x, F_EPS);
        float ha = fmaxf(an.w - an.y, F_EPS);
        float cxa = an.x + 0.5f * wa;
        float cya = an.y + 0.5f * ha;
        float wt = fmaxf(bx2 - bx1, F_EPS);
        float ht = fmaxf(by2 - by1, F_EPS);
        float cxt = bx1 + 0.5f * (bx2 - bx1);
        float cyt = by1 + 0.5f * (by2 - by1);
        float tg0 = (cxt - cxa) / wa;
        float tg1 = (cyt - cya) / ha;
        float tg2 = logf(wt / wa);
        float tg3 = logf(ht / ha);
        float d0 = fabsf(tg0 - bp.x), d1 = fabsf(tg1 - bp.y);
        float d2 = fabsf(tg2 - bp.z), d3 = fabsf(tg3 - bp.w);
        box += (d0 < SL1_BETA) ? (0.5f * d0 * d0 / SL1_BETA) : (d0 - 0.5f * SL1_BETA);
        box += (d1 < SL1_BETA) ? (0.5f * d1 * d1 / SL1_BETA) : (d1 - 0.5f * SL1_BETA);
        box += (d2 < SL1_BETA) ? (0.5f * d2 * d2 / SL1_BETA) : (d2 - 0.5f * SL1_BETA);
        box += (d3 < SL1_BETA) ? (0.5f * d3 * d3 / SL1_BETA) : (d3 - 0.5f * SL1_BETA);
    }

    // block reduce
    unsigned full = 0xFFFFFFFFu;
    #pragma unroll
    for (int o = 16; o > 0; o >>= 1) {
        cls += __shfl_down_sync(full, cls, o);
        box += __shfl_down_sync(full, box, o);
    }
    __shared__ float wc[8], wb[8];
    int w = threadIdx.x >> 5, lane = threadIdx.x & 31;
    if (lane == 0) { wc[w] = cls; wb[w] = box; }
    __syncthreads();
    if (threadIdx.x == 0) {
        float c = 0.f, b = 0.f;
        #pragma unroll
        for (int i = 0; i < 8; i++) { c += wc[i]; b += wb[i]; }
        g_qcls[blockIdx.x] = c;
        g_qbox[blockIdx.x] = b;
    }

    // last finishing block: final reduce (MLP-batched float4 loads) + output + resets
    __syncthreads();
    __threadfence();
    __shared__ bool slast;
    if (threadIdx.x == 0)
        slast = (atomicAdd(&g_doneB, 1u) == (unsigned)(QB - 1));
    __syncthreads();
    if (!slast) return;

    __shared__ double sc[256], sb2[256];
    int tid = threadIdx.x;
    double c = 0.0, b = 0.0;
    {
        const float4* pc4 = (const float4*)g_pcls;     // SBX/4 = 1280
        #pragma unroll 5
        for (int i = tid; i < SBX / 4; i += 256) {
            float4 v = pc4[i];
            c += (double)((v.x + v.y) + (v.z + v.w));
        }
        const float4* qc4 = (const float4*)g_qcls;     // QB/4 = 512
        const float4* qb4 = (const float4*)g_qbox;
        #pragma unroll 2
        for (int i = tid; i < QB / 4; i += 256) {
            float4 v = qc4[i];
            float4 u = qb4[i];
            c += (double)((v.x + v.y) + (v.z + v.w));
            b += (double)((u.x + u.y) + (u.z + u.w));
        }
    }
    sc[tid] = c; sb2[tid] = b;
    __syncthreads();
    for (int s = 128; s > 0; s >>= 1) {
        if (tid < s) { sc[tid] += sc[tid + s]; sb2[tid] += sb2[tid + s]; }
        __syncthreads();
    }
    if (tid == 0) {
        double avg = 0.0;
        for (int nn = 0; nn < Nn; nn++) {
            double p = (double)g_poscnt[nn];
            avg += (p > 1.0) ? p : 1.0;
        }
        float clsO = (float)(sc[0] / avg);
        float boxO = (float)(sb2[0] / avg);
        if (isnan(clsO) || isinf(clsO)) clsO = 0.f;
        if (isnan(boxO) || isinf(boxO)) boxO = 0.f;
        out[0] = clsO;
        out[1] = boxO;
    }
    // resets for next graph replay
    __syncthreads();
    if (tid == 0) { g_done1 = 0; g_doneB = 0; g_npos = 0; g_nign = 0; }
    if (tid < Nn) g_poscnt[tid] = 0;
    for (int i = tid; i < Nn * Tt; i += 256) g_gtkey[i] = 0ull;
}

// ---------------- launch ----------------
extern "C" void kernel_launch(void* const* d_in, const int* in_sizes, int n_in,
                              void* d_out, int out_size) {
    const float*  y_true    = (const float*)d_in[0];
    const float*  bbox_true = (const float*)d_in[1];
    const float*  y_pred    = (const float*)d_in[2];
    const float4* bbox_pred = (const float4*)d_in[3];
    const float4* anchors   = (const float4*)d_in[4];
    float* out = (float*)d_out;

    kA<<<TOTB, 256>>>(anchors, (const float4*)bbox_true, y_true,
                      (const float4*)y_pred);
    kB<<<QB, 256>>>((const float4*)y_pred, anchors, bbox_pred, bbox_true, out);
}

// round 14
// speedup vs baseline: 1.6455x; 1.0274x over previous
#include <cuda_runtime.h>
#include <math.h>

#define Nn 8
#define Tt 64
#define Aa 65536
#define Cc 80
#define NFLT4 (Aa * (Cc / 4))          // float4s of y_pred per image = 1,310,720
#define ITER 8
#define SBX_PER_N 640                   // stream blocks per image
#define SBb (SBX_PER_N * Nn)            // 5120 stream blocks
#define AB ((Aa / 256) * Nn)            // 2048 assignment blocks
#define CB 2048                         // correction blocks
#define TOTB (AB + SBb + CB + 1)        // + 1 final block

#define F_EPS 1e-6f
#define SL1_BETA (1.0f / 9.0f)
#define LN2 0.69314718055994531f
#define IGN_FLAG (1 << 30)

// ---------------- scratch (device globals; no allocation) ----------------
__device__ int            g_state[Nn * Aa];   // 0=ignore 1=neg 2=pos
__device__ int            g_asg[Nn * Aa];     // bit30 = override, low bits = gt index t
__device__ int            g_nvalid[Nn];
__device__ unsigned char  g_vt[Nn * Tt];
__device__ unsigned char  g_label[Nn * Tt];
__device__ unsigned long long g_gtkey[Nn * Tt];
__device__ int            g_poscnt[Nn];
__device__ __align__(16) float g_pcls[SBb];
__device__ __align__(16) float g_qcls[CB];
__device__ __align__(16) float g_qbox[CB];
__device__ int            g_ignlist[Nn * Aa];
__device__ int            g_poslist[Nn * Aa];
__device__ int            g_nign;
__device__ int            g_npos;
__device__ unsigned       g_done1;    // assignment blocks completed
__device__ unsigned       g_lqdone;   // LQ tail complete (lists final)
__device__ unsigned       g_doneS;    // stream blocks completed
__device__ unsigned       g_doneC;    // correction blocks completed

// ---------------- helpers ----------------
__device__ __forceinline__ float rcp_approx(float x) {
    float r; asm("rcp.approx.f32 %0, %1;" : "=f"(r) : "f"(x)); return r;
}
__device__ __forceinline__ float ex2a(float x) {
    float r; asm("ex2.approx.f32 %0, %1;" : "=f"(r) : "f"(x)); return r;
}
__device__ __forceinline__ float lg2a(float x) {
    float r; asm("lg2.approx.f32 %0, %1;" : "=f"(r) : "f"(x)); return r;
}
__device__ __forceinline__ float slctf(float a, float b, float c) {
    float r; asm("slct.f32.f32 %0, %1, %2, %3;" : "=f"(r) : "f"(a), "f"(b), "f"(c)); return r;
}

// Variant A: 3 MUFU (EX2, RCP, LG2)
__device__ __forceinline__ float focal_A(float l) {
    float t  = ex2a(fabsf(l) * -1.44269504f);   // e^{-|l|}
    float u  = 1.0f + t;
    float r  = rcp_approx(u);
    float w  = r * r;
    float tr = t * r;
    float v  = tr * tr;
    float p2 = slctf(w, v, l);                   // p^2
    float ce = fmaf(lg2a(u), (float)LN2, fmaxf(l, 0.f)); // softplus(l)
    return p2 * ce;
}

// Variant B: 2 MUFU (EX2, LG2), reciprocal on FMA pipe
__device__ __forceinline__ float focal_B(float l) {
    float t  = ex2a(fabsf(l) * -1.44269504f);
    float u  = 1.0f + t;
    float x  = fmaf(2.0f, u, -3.0f);
    float r  = fmaf(-0.028572f, x, 0.08326f);
    r = fmaf(r, x, -0.22121f);
    r = fmaf(r, x, 0.66548f);
    r = r * fmaf(-u, r, 2.0f);                   // Newton: rel err ~2e-6
    float w  = r * r;
    float tr = t * r;
    float v  = tr * tr;
    float p2 = slctf(w, v, l);
    float ce = fmaf(lg2a(u), (float)LN2, fmaxf(l, 0.f));
    return p2 * ce;
}

__device__ __forceinline__ void spin_ge(volatile unsigned* p, unsigned v) {
    while (*p < v) __nanosleep(200);
}

// ---------------- single fused launch ----------------
__global__ void __launch_bounds__(256, 4)
kAll(const float4* __restrict__ anchors,
     const float4* __restrict__ bb,
     const float* __restrict__ y_true,
     const float4* __restrict__ yp4,
     const float4* __restrict__ bbp4,
     const float* __restrict__ bbox_true,
     float* __restrict__ out) {
    int bid = blockIdx.x;
    int tid = threadIdx.x;

    // ================= STREAM BLOCKS =================
    if (bid >= AB && bid < AB + SBb) {
        int sb = bid - AB;
        int n = sb / SBX_PER_N;
        int bx = sb - n * SBX_PER_N;
        const float4* yp = yp4 + (size_t)n * NFLT4 + bx * (256 * ITER);
        float acc0 = 0.f, acc1 = 0.f;
        #pragma unroll
        for (int i = 0; i < ITER; i++) {
            float4 vv = yp[i * 256 + tid];
            acc0 += focal_A(vv.x) + focal_A(vv.z);
            acc1 += focal_B(vv.y) + focal_B(vv.w);
        }
        float clsl = acc0 + acc1;
        unsigned full = 0xFFFFFFFFu;
        #pragma unroll
        for (int o = 16; o > 0; o >>= 1)
            clsl += __shfl_down_sync(full, clsl, o);
        __shared__ float wc[8];
        int w = tid >> 5, lane = tid & 31;
        if (lane == 0) wc[w] = clsl;
        __syncthreads();
        if (tid == 0) {
            float c = 0.f;
            #pragma unroll
            for (int i = 0; i < 8; i++) c += wc[i];
            g_pcls[sb] = 0.75f * c;
            __threadfence();
            atomicAdd(&g_doneS, 1u);
        }
        return;
    }

    // ================= CORRECTION BLOCKS =================
    if (bid >= AB + SBb && bid < AB + SBb + CB) {
        int cb = bid - AB - SBb;
        if (tid == 0) spin_ge(&g_lqdone, 1u);       // lists final after LQ tail
        __syncthreads();
        __threadfence();

        float cls = 0.f, box = 0.f;
        int gtid = cb * 256 + tid;
        const int stride = CB * 256;

        int nI = g_nign;
        int nItems = nI * 20;
        #pragma unroll 4
        for (int it = gtid; it < nItems; it += stride) {
            int e = it / 20;
            int qq = it - e * 20;
            int idx = g_ignlist[e];
            int n = idx >> 16;
            int a = idx & (Aa - 1);
            float4 vv = yp4[(size_t)n * NFLT4 + (size_t)a * 20 + qq];
            float S = focal_A(vv.x) + focal_B(vv.y) + focal_A(vv.z) + focal_B(vv.w);
            cls = fmaf(-0.75f, S, cls);
        }

        int nP = g_npos;
        for (int e = gtid; e < nP; e += stride) {
            int ent = g_poslist[e];
            int idx = ent & ~IGN_FLAG;
            int n = idx >> 16;
            int a = idx & (Aa - 1);
            const float4* yp = yp4 + (size_t)n * NFLT4 + (size_t)a * 20;

            if (ent & IGN_FLAG) {
                float S = 0.f;
                #pragma unroll 4
                for (int qq = 0; qq < 20; qq++) {
                    float4 vv = yp[qq];
                    S += focal_A(vv.x) + focal_B(vv.y) + focal_A(vv.z) + focal_B(vv.w);
                }
                cls = fmaf(0.75f, S, cls);
            }

            int v = g_asg[idx];
            int asg = (v & 0x40000000) ? (v & 0xFF) : v;
            int label = (int)g_label[n * Tt + asg];
            float4 vv = yp[label >> 2];
            int j = label & 3;
            float lsel = (j == 0) ? vv.x : ((j == 1) ? vv.y : ((j == 2) ? vv.z : vv.w));
            {
                float mm = fabsf(lsel);
                float em = __expf(-mm);
                float uu = 1.0f + em;
                float r  = rcp_approx(uu);
                float lgv = __logf(uu);
                float p  = (lsel >= 0.f) ? r : em * r;
                float qd = 1.0f - p;
                float ce  = lgv + fmaxf(lsel, 0.f);
                float cep = lgv + fmaxf(-lsel, 0.f);
                cls += 0.25f * qd * qd * cep - 0.75f * p * p * ce;
            }
            float4 an = anchors[a];
            float4 bp = bbp4[idx];
            const float* bt = bbox_true + ((size_t)n * Tt + asg) * 4;
            float bx1 = bt[0], by1 = bt[1], bx2 = bt[2], by2 = bt[3];
            float wa = fmaxf(an.z - an.x, F_EPS);
            float ha = fmaxf(an.w - an.y, F_EPS);
            float cxa = an.x + 0.5f * wa;
            float cya = an.y + 0.5f * ha;
            float wt = fmaxf(bx2 - bx1, F_EPS);
            float ht = fmaxf(by2 - by1, F_EPS);
            float cxt = bx1 + 0.5f * (bx2 - bx1);
            float cyt = by1 + 0.5f * (by2 - by1);
            float tg0 = (cxt - cxa) / wa;
            float tg1 = (cyt - cya) / ha;
            float tg2 = logf(wt / wa);
            float tg3 = logf(ht / ha);
            float d0 = fabsf(tg0 - bp.x), d1 = fabsf(tg1 - bp.y);
            float d2 = fabsf(tg2 - bp.z), d3 = fabsf(tg3 - bp.w);
            box += (d0 < SL1_BETA) ? (0.5f * d0 * d0 / SL1_BETA) : (d0 - 0.5f * SL1_BETA);
            box += (d1 < SL1_BETA) ? (0.5f * d1 * d1 / SL1_BETA) : (d1 - 0.5f * SL1_BETA);
            box += (d2 < SL1_BETA) ? (0.5f * d2 * d2 / SL1_BETA) : (d2 - 0.5f * SL1_BETA);
            box += (d3 < SL1_BETA) ? (0.5f * d3 * d3 / SL1_BETA) : (d3 - 0.5f * SL1_BETA);
        }

        unsigned full = 0xFFFFFFFFu;
        #pragma unroll
        for (int o = 16; o > 0; o >>= 1) {
            cls += __shfl_down_sync(full, cls, o);
            box += __shfl_down_sync(full, box, o);
        }
        __shared__ float wc[8], wb[8];
        int w = tid >> 5, lane = tid & 31;
        if (lane == 0) { wc[w] = cls; wb[w] = box; }
        __syncthreads();
        if (tid == 0) {
            float c = 0.f, b = 0.f;
            #pragma unroll
            for (int i = 0; i < 8; i++) { c += wc[i]; b += wb[i]; }
            g_qcls[cb] = c;
            g_qbox[cb] = b;
            __threadfence();
            atomicAdd(&g_doneC, 1u);
        }
        return;
    }

    // ================= FINAL BLOCK =================
    if (bid == AB + SBb + CB) {
        if (tid == 0) {
            spin_ge(&g_doneS, (unsigned)SBb);
            spin_ge(&g_doneC, (unsigned)CB);
        }
        __syncthreads();
        __threadfence();

        __shared__ double sc[256], sb2[256];
        double c = 0.0, b = 0.0;
        {
            const float4* pc4 = (const float4*)g_pcls;     // 1280
            #pragma unroll 5
            for (int i = tid; i < SBb / 4; i += 256) {
                float4 v = pc4[i];
                c += (double)((v.x + v.y) + (v.z + v.w));
            }
            const float4* qc4 = (const float4*)g_qcls;     // 512
            const float4* qb4 = (const float4*)g_qbox;
            #pragma unroll 2
            for (int i = tid; i < CB / 4; i += 256) {
                float4 v = qc4[i];
                float4 u = qb4[i];
                c += (double)((v.x + v.y) + (v.z + v.w));
                b += (double)((u.x + u.y) + (u.z + u.w));
            }
        }
        sc[tid] = c; sb2[tid] = b;
        __syncthreads();
        for (int s = 128; s > 0; s >>= 1) {
            if (tid < s) { sc[tid] += sc[tid + s]; sb2[tid] += sb2[tid + s]; }
            __syncthreads();
        }
        if (tid == 0) {
            double avg = 0.0;
            for (int nn = 0; nn < Nn; nn++) {
                double p = (double)g_poscnt[nn];
                avg += (p > 1.0) ? p : 1.0;
            }
            float clsO = (float)(sc[0] / avg);
            float boxO = (float)(sb2[0] / avg);
            if (isnan(clsO) || isinf(clsO)) clsO = 0.f;
            if (isnan(boxO) || isinf(boxO)) boxO = 0.f;
            out[0] = clsO;
            out[1] = boxO;
        }
        __syncthreads();
        // resets for next graph replay
        if (tid == 0) {
            g_done1 = 0; g_lqdone = 0; g_doneS = 0; g_doneC = 0;
            g_npos = 0; g_nign = 0;
        }
        if (tid < Nn) g_poscnt[tid] = 0;
        for (int i = tid; i < Nn * Tt; i += 256) g_gtkey[i] = 0ull;
        return;
    }

    // ================= ASSIGNMENT BLOCKS (bid < AB) =================
    int n = bid >> 8;
    int axb = bid & 255;

    __shared__ float4 sbox[Tt];
    __shared__ float  sarea[Tt];
    __shared__ unsigned char svt[Tt];
    __shared__ unsigned long long swkey[8][Tt];
    __shared__ unsigned smask[2];
    __shared__ int snv;

    float4 myb; bool myvalid = false; unsigned mk = 0;
    if (tid < 64) {
        myb = bb[n * Tt + tid];
        myvalid = (myb.x > 0.f) || (myb.y > 0.f) || (myb.z > 0.f) || (myb.w > 0.f);
        mk = __ballot_sync(0xFFFFFFFFu, myvalid);
        if ((tid & 31) == 0) smask[tid >> 5] = mk;
    }
    if (axb == 0 && tid >= 64 && tid < 128) {
        int r = n * Tt + (tid - 64);
        const float4* row = (const float4*)(y_true + (size_t)r * Cc);
        int lab = 0;
        #pragma unroll 4
        for (int qq = 0; qq < Cc / 4; qq++) {
            float4 v = row[qq];
            if (v.x > 0.5f) lab = 4 * qq;
            if (v.y > 0.5f) lab = 4 * qq + 1;
            if (v.z > 0.5f) lab = 4 * qq + 2;
            if (v.w > 0.5f) lab = 4 * qq + 3;
        }
        g_label[r] = (unsigned char)lab;
    }
    __syncthreads();
    if (tid < 64 && myvalid) {
        int pos = __popc(mk & ((1u << (tid & 31)) - 1)) +
                  ((tid >= 32) ? __popc(smask[0]) : 0);
        sbox[pos]  = myb;
        sarea[pos] = fmaxf(myb.z - myb.x, 0.f) * fmaxf(myb.w - myb.y, 0.f);
        svt[pos]   = (unsigned char)tid;
        if (axb == 0) g_vt[n * Tt + pos] = (unsigned char)tid;
    }
    if (tid == 0) {
        snv = __popc(smask[0]) + __popc(smask[1]);
        if (axb == 0) g_nvalid[n] = snv;
    }
    __syncthreads();
    int nv = snv;

    int a = axb * 256 + tid;
    float4 an = anchors[a];
    float a2 = fmaxf(an.z - an.x, 0.f) * fmaxf(an.w - an.y, 0.f);
    unsigned lane = tid & 31;
    int w = tid >> 5;

    float best = -1.0f; int arg = 0;
    for (int k = 0; k < nv; k++) {
        float4 b = sbox[k];
        float lx = fmaxf(b.x, an.x), ly = fmaxf(b.y, an.y);
        float rx = fminf(b.z, an.z), ry = fminf(b.w, an.w);
        float iw = fmaxf(rx - lx, 0.f), ih = fmaxf(ry - ly, 0.f);
        float inter = iw * ih;
        float uni = sarea[k] + a2 - inter;
        float iou = __fdividef(inter, fmaxf(uni, 1e-10f));  // approx div
        if (iou > best) { best = iou; arg = svt[k]; }       // first-max (smallest t)

        unsigned ib = __float_as_uint(iou);
        unsigned mx = __reduce_max_sync(0xFFFFFFFFu, ib);
        unsigned msk = __ballot_sync(0xFFFFFFFFu, ib == mx);
        if (lane == (unsigned)(__ffs(msk) - 1))
            swkey[w][k] = ((unsigned long long)mx << 32) |
                          (unsigned long long)(~(unsigned)a);
    }
    __syncthreads();

    int idx = n * Aa + a;
    int st = (best >= 0.5f) ? 2 : ((best < 0.4f) ? 1 : 0);
    g_asg[idx]   = arg;
    g_state[idx] = st;

    // warp-aggregated list appends
    {
        unsigned bpos = __ballot_sync(0xFFFFFFFFu, st == 2);
        unsigned bign = __ballot_sync(0xFFFFFFFFu, st == 0);
        unsigned lmask = (1u << lane) - 1u;
        int basep = 0, basei = 0;
        if (lane == 0) {
            if (bpos) {
                basep = atomicAdd(&g_npos, __popc(bpos));
                atomicAdd(&g_poscnt[n], __popc(bpos));
            }
            if (bign) basei = atomicAdd(&g_nign, __popc(bign));
        }
        basep = __shfl_sync(0xFFFFFFFFu, basep, 0);
        basei = __shfl_sync(0xFFFFFFFFu, basei, 0);
        if (st == 2) g_poslist[basep + __popc(bpos & lmask)] = idx;
        if (st == 0) g_ignlist[basei + __popc(bign & lmask)] = idx;
    }

    if (tid < nv) {
        unsigned long long m = swkey[0][tid];
        #pragma unroll
        for (int ww = 1; ww < 8; ww++) {
            unsigned long long o = swkey[ww][tid];
            if (o > m) m = o;
        }
        if ((m >> 32) != 0)
            atomicMax(&g_gtkey[n * Tt + tid], m);
    }

    // fused low-quality override: last finishing assignment block applies all
    __syncthreads();
    __threadfence();
    __shared__ bool slast;
    if (tid == 0)
        slast = (atomicAdd(&g_done1, 1u) == (unsigned)(AB - 1));
    __syncthreads();
    if (slast) {
        for (int idx2 = tid; idx2 < Nn * Tt; idx2 += 256) {
            int nn = idx2 >> 6, k = idx2 & 63;
            if (k < g_nvalid[nn]) {
                unsigned long long key = g_gtkey[nn * Tt + k];
                if ((key >> 32) != 0) {
                    int aa = (int)(~(unsigned)(key & 0xFFFFFFFFull));
                    int t = g_vt[nn * Tt + k];
                    int p = nn * Aa + aa;
                    atomicMax(&g_asg[p], 0x40000000 | t);
                    int old = atomicExch(&g_state[p], 2);
                    if (old != 2) {
                        int pp = atomicAdd(&g_npos, 1);
                        g_poslist[pp] = p | ((old == 0) ? IGN_FLAG : 0);
                        atomicAdd(&g_poscnt[nn], 1);
                    }
                }
            }
        }
        __syncthreads();
        __threadfence();
        if (tid == 0) atomicExch(&g_lqdone, 1u);   // release: lists final
    }
}

// ---------------- launch ----------------
extern "C" void kernel_launch(void* const* d_in, const int* in_sizes, int n_in,
                              void* d_out, int out_size) {
    const float*  y_true    = (const float*)d_in[0];
    const float*  bbox_true = (const float*)d_in[1];
    const float*  y_pred    = (const float*)d_in[2];
    const float4* bbox_pred = (const float4*)d_in[3];
    const float4* anchors   = (const float4*)d_in[4];
    float* out = (float*)d_out;

    kAll<<<TOTB, 256>>>(anchors, (const float4*)bbox_true, y_true,
                        (const float4*)y_pred, bbox_pred, bbox_true, out);
}

// round 15
// speedup vs baseline: 1.8631x; 1.1322x over previous
#include <cuda_runtime.h>
#include <math.h>

#define Nn 8
#define Tt 64
#define Aa 65536
#define Cc 80
#define NFLT4 (Aa * (Cc / 4))          // float4s of y_pred per image = 1,310,720
#define ITER 8
#define SBX_PER_N 640                   // stream blocks per image
#define SBb (SBX_PER_N * Nn)            // 5120 stream blocks
#define AB ((Aa / 256) * Nn)            // 2048 assignment blocks
#define CB 2048                         // correction blocks
#define TOTB (AB + SBb + CB + 1)        // + 1 final block

#define F_EPS 1e-6f
#define SL1_BETA (1.0f / 9.0f)
#define LN2 0.69314718055994531f
#define IGN_FLAG (1 << 30)

// ---------------- scratch (device globals; no allocation) ----------------
__device__ int            g_state[Nn * Aa];   // 0=ignore 1=neg 2=pos
__device__ int            g_asg[Nn * Aa];     // bit30 = override, low bits = gt index t
__device__ int            g_nvalid[Nn];
__device__ unsigned char  g_vt[Nn * Tt];
__device__ unsigned char  g_label[Nn * Tt];
__device__ unsigned long long g_gtkey[Nn * Tt];
__device__ int            g_poscnt[Nn];
__device__ __align__(16) float g_pcls[SBb];
__device__ __align__(16) float g_qcls[CB];
__device__ __align__(16) float g_qbox[CB];
__device__ int            g_ignlist[Nn * Aa];
__device__ int            g_poslist[Nn * Aa];
__device__ int            g_nign;
__device__ int            g_npos;
__device__ unsigned       g_done1;    // assignment blocks completed
__device__ unsigned       g_lqdone;   // LQ tail complete (lists final)
__device__ unsigned       g_doneS;    // stream blocks completed
__device__ unsigned       g_doneC;    // correction blocks completed

// ---------------- helpers ----------------
__device__ __forceinline__ float rcp_approx(float x) {
    float r; asm("rcp.approx.f32 %0, %1;" : "=f"(r) : "f"(x)); return r;
}
__device__ __forceinline__ float ex2a(float x) {
    float r; asm("ex2.approx.f32 %0, %1;" : "=f"(r) : "f"(x)); return r;
}
__device__ __forceinline__ float lg2a(float x) {
    float r; asm("lg2.approx.f32 %0, %1;" : "=f"(r) : "f"(x)); return r;
}
__device__ __forceinline__ float slctf(float a, float b, float c) {
    float r; asm("slct.f32.f32 %0, %1, %2, %3;" : "=f"(r) : "f"(a), "f"(b), "f"(c)); return r;
}

// Variant A: 3 MUFU (EX2, RCP, LG2)
__device__ __forceinline__ float focal_A(float l) {
    float t  = ex2a(fabsf(l) * -1.44269504f);   // e^{-|l|}
    float u  = 1.0f + t;
    float r  = rcp_approx(u);
    float w  = r * r;
    float tr = t * r;
    float v  = tr * tr;
    float p2 = slctf(w, v, l);                   // p^2
    float ce = fmaf(lg2a(u), (float)LN2, fmaxf(l, 0.f)); // softplus(l)
    return p2 * ce;
}

// Variant B: 2 MUFU (EX2, LG2), reciprocal on FMA pipe
__device__ __forceinline__ float focal_B(float l) {
    float t  = ex2a(fabsf(l) * -1.44269504f);
    float u  = 1.0f + t;
    float x  = fmaf(2.0f, u, -3.0f);
    float r  = fmaf(-0.028572f, x, 0.08326f);
    r = fmaf(r, x, -0.22121f);
    r = fmaf(r, x, 0.66548f);
    r = r * fmaf(-u, r, 2.0f);                   // Newton: rel err ~2e-6
    float w  = r * r;
    float tr = t * r;
    float v  = tr * tr;
    float p2 = slctf(w, v, l);
    float ce = fmaf(lg2a(u), (float)LN2, fmaxf(l, 0.f));
    return p2 * ce;
}

__device__ __forceinline__ void spin_ge(volatile unsigned* p, unsigned v) {
    while (*p < v) __nanosleep(200);
}

// ---------------- single fused launch; regs capped for stream occupancy ----------------
__global__ void __launch_bounds__(256, 6)
kAll(const float4* __restrict__ anchors,
     const float4* __restrict__ bb,
     const float* __restrict__ y_true,
     const float4* __restrict__ yp4,
     const float4* __restrict__ bbp4,
     const float* __restrict__ bbox_true,
     float* __restrict__ out) {
    int bid = blockIdx.x;
    int tid = threadIdx.x;

    // ================= STREAM BLOCKS =================
    if (bid >= AB && bid < AB + SBb) {
        int sb = bid - AB;
        int n = sb / SBX_PER_N;
        int bx = sb - n * SBX_PER_N;
        const float4* yp = yp4 + (size_t)n * NFLT4 + bx * (256 * ITER);
        float acc0 = 0.f, acc1 = 0.f;
        #pragma unroll
        for (int i = 0; i < ITER; i++) {
            float4 vv = yp[i * 256 + tid];
            acc0 += focal_A(vv.x) + focal_A(vv.z);
            acc1 += focal_B(vv.y) + focal_B(vv.w);
        }
        float clsl = acc0 + acc1;
        unsigned full = 0xFFFFFFFFu;
        #pragma unroll
        for (int o = 16; o > 0; o >>= 1)
            clsl += __shfl_down_sync(full, clsl, o);
        __shared__ float wc[8];
        int w = tid >> 5, lane = tid & 31;
        if (lane == 0) wc[w] = clsl;
        __syncthreads();
        if (tid == 0) {
            float c = 0.f;
            #pragma unroll
            for (int i = 0; i < 8; i++) c += wc[i];
            g_pcls[sb] = 0.75f * c;
            __threadfence();
            atomicAdd(&g_doneS, 1u);
        }
        return;
    }

    // ================= CORRECTION BLOCKS =================
    if (bid >= AB + SBb && bid < AB + SBb + CB) {
        int cb = bid - AB - SBb;
        if (tid == 0) spin_ge(&g_lqdone, 1u);       // lists final after LQ tail
        __syncthreads();
        __threadfence();

        float cls = 0.f, box = 0.f;
        int gtid = cb * 256 + tid;
        const int stride = CB * 256;

        int nI = g_nign;
        int nItems = nI * 20;
        #pragma unroll 4
        for (int it = gtid; it < nItems; it += stride) {
            int e = it / 20;
            int qq = it - e * 20;
            int idx = g_ignlist[e];
            int n = idx >> 16;
            int a = idx & (Aa - 1);
            float4 vv = yp4[(size_t)n * NFLT4 + (size_t)a * 20 + qq];
            float S = focal_A(vv.x) + focal_B(vv.y) + focal_A(vv.z) + focal_B(vv.w);
            cls = fmaf(-0.75f, S, cls);
        }

        int nP = g_npos;
        for (int e = gtid; e < nP; e += stride) {
            int ent = g_poslist[e];
            int idx = ent & ~IGN_FLAG;
            int n = idx >> 16;
            int a = idx & (Aa - 1);
            const float4* yp = yp4 + (size_t)n * NFLT4 + (size_t)a * 20;

            if (ent & IGN_FLAG) {
                float S = 0.f;
                #pragma unroll 4
                for (int qq = 0; qq < 20; qq++) {
                    float4 vv = yp[qq];
                    S += focal_A(vv.x) + focal_B(vv.y) + focal_A(vv.z) + focal_B(vv.w);
                }
                cls = fmaf(0.75f, S, cls);
            }

            int v = g_asg[idx];
            int asg = (v & 0x40000000) ? (v & 0xFF) : v;
            int label = (int)g_label[n * Tt + asg];
            float4 vv = yp[label >> 2];
            int j = label & 3;
            float lsel = (j == 0) ? vv.x : ((j == 1) ? vv.y : ((j == 2) ? vv.z : vv.w));
            {
                float mm = fabsf(lsel);
                float em = __expf(-mm);
                float uu = 1.0f + em;
                float r  = rcp_approx(uu);
                float lgv = __logf(uu);
                float p  = (lsel >= 0.f) ? r : em * r;
                float qd = 1.0f - p;
                float ce  = lgv + fmaxf(lsel, 0.f);
                float cep = lgv + fmaxf(-lsel, 0.f);
                cls += 0.25f * qd * qd * cep - 0.75f * p * p * ce;
            }
            float4 an = anchors[a];
            float4 bp = bbp4[idx];
            const float* bt = bbox_true + ((size_t)n * Tt + asg) * 4;
            float bx1 = bt[0], by1 = bt[1], bx2 = bt[2], by2 = bt[3];
            float wa = fmaxf(an.z - an.x, F_EPS);
            float ha = fmaxf(an.w - an.y, F_EPS);
            float cxa = an.x + 0.5f * wa;
            float cya = an.y + 0.5f * ha;
            float wt = fmaxf(bx2 - bx1, F_EPS);
            float ht = fmaxf(by2 - by1, F_EPS);
            float cxt = bx1 + 0.5f * (bx2 - bx1);
            float cyt = by1 + 0.5f * (by2 - by1);
            float tg0 = (cxt - cxa) / wa;
            float tg1 = (cyt - cya) / ha;
            float tg2 = logf(wt / wa);
            float tg3 = logf(ht / ha);
            float d0 = fabsf(tg0 - bp.x), d1 = fabsf(tg1 - bp.y);
            float d2 = fabsf(tg2 - bp.z), d3 = fabsf(tg3 - bp.w);
            box += (d0 < SL1_BETA) ? (0.5f * d0 * d0 / SL1_BETA) : (d0 - 0.5f * SL1_BETA);
            box += (d1 < SL1_BETA) ? (0.5f * d1 * d1 / SL1_BETA) : (d1 - 0.5f * SL1_BETA);
            box += (d2 < SL1_BETA) ? (0.5f * d2 * d2 / SL1_BETA) : (d2 - 0.5f * SL1_BETA);
            box += (d3 < SL1_BETA) ? (0.5f * d3 * d3 / SL1_BETA) : (d3 - 0.5f * SL1_BETA);
        }

        unsigned full = 0xFFFFFFFFu;
        #pragma unroll
        for (int o = 16; o > 0; o >>= 1) {
            cls += __shfl_down_sync(full, cls, o);
            box += __shfl_down_sync(full, box, o);
        }
        __shared__ float wc[8], wb[8];
        int w = tid >> 5, lane = tid & 31;
        if (lane == 0) { wc[w] = cls; wb[w] = box; }
        __syncthreads();
        if (tid == 0) {
            float c = 0.f, b = 0.f;
            #pragma unroll
            for (int i = 0; i < 8; i++) { c += wc[i]; b += wb[i]; }
            g_qcls[cb] = c;
            g_qbox[cb] = b;
            __threadfence();
            atomicAdd(&g_doneC, 1u);
        }
        return;
    }

    // ================= FINAL BLOCK =================
    if (bid == AB + SBb + CB) {
        if (tid == 0) {
            spin_ge(&g_doneS, (unsigned)SBb);
            spin_ge(&g_doneC, (unsigned)CB);
        }
        __syncthreads();
        __threadfence();

        __shared__ double sc[256], sb2[256];
        double c = 0.0, b = 0.0;
        {
            const float4* pc4 = (const float4*)g_pcls;     // 1280
            #pragma unroll 5
            for (int i = tid; i < SBb / 4; i += 256) {
                float4 v = pc4[i];
                c += (double)((v.x + v.y) + (v.z + v.w));
            }
            const float4* qc4 = (const float4*)g_qcls;     // 512
            const float4* qb4 = (const float4*)g_qbox;
            #pragma unroll 2
            for (int i = tid; i < CB / 4; i += 256) {
                float4 v = qc4[i];
                float4 u = qb4[i];
                c += (double)((v.x + v.y) + (v.z + v.w));
                b += (double)((u.x + u.y) + (u.z + u.w));
            }
        }
        sc[tid] = c; sb2[tid] = b;
        __syncthreads();
        for (int s = 128; s > 0; s >>= 1) {
            if (tid < s) { sc[tid] += sc[tid + s]; sb2[tid] += sb2[tid + s]; }
            __syncthreads();
        }
        if (tid == 0) {
            double avg = 0.0;
            for (int nn = 0; nn < Nn; nn++) {
                double p = (double)g_poscnt[nn];
                avg += (p > 1.0) ? p : 1.0;
            }
            float clsO = (float)(sc[0] / avg);
            float boxO = (float)(sb2[0] / avg);
            if (isnan(clsO) || isinf(clsO)) clsO = 0.f;
            if (isnan(boxO) || isinf(boxO)) boxO = 0.f;
            out[0] = clsO;
            out[1] = boxO;
        }
        __syncthreads();
        // resets for next graph replay
        if (tid == 0) {
            g_done1 = 0; g_lqdone = 0; g_doneS = 0; g_doneC = 0;
            g_npos = 0; g_nign = 0;
        }
        if (tid < Nn) g_poscnt[tid] = 0;
        for (int i = tid; i < Nn * Tt; i += 256) g_gtkey[i] = 0ull;
        return;
    }

    // ================= ASSIGNMENT BLOCKS (bid < AB) =================
    int n = bid >> 8;
    int axb = bid & 255;

    __shared__ float4 sbox[Tt];
    __shared__ float  sarea[Tt];
    __shared__ unsigned char svt[Tt];
    __shared__ unsigned long long swkey[8][Tt];
    __shared__ unsigned smask[2];
    __shared__ int snv;

    float4 myb; bool myvalid = false; unsigned mk = 0;
    if (tid < 64) {
        myb = bb[n * Tt + tid];
        myvalid = (myb.x > 0.f) || (myb.y > 0.f) || (myb.z > 0.f) || (myb.w > 0.f);
        mk = __ballot_sync(0xFFFFFFFFu, myvalid);
        if ((tid & 31) == 0) smask[tid >> 5] = mk;
    }
    if (axb == 0 && tid >= 64 && tid < 128) {
        int r = n * Tt + (tid - 64);
        const float4* row = (const float4*)(y_true + (size_t)r * Cc);
        int lab = 0;
        #pragma unroll 4
        for (int qq = 0; qq < Cc / 4; qq++) {
            float4 v = row[qq];
            if (v.x > 0.5f) lab = 4 * qq;
            if (v.y > 0.5f) lab = 4 * qq + 1;
            if (v.z > 0.5f) lab = 4 * qq + 2;
            if (v.w > 0.5f) lab = 4 * qq + 3;
        }
        g_label[r] = (unsigned char)lab;
    }
    __syncthreads();
    if (tid < 64 && myvalid) {
        int pos = __popc(mk & ((1u << (tid & 31)) - 1)) +
                  ((tid >= 32) ? __popc(smask[0]) : 0);
        sbox[pos]  = myb;
        sarea[pos] = fmaxf(myb.z - myb.x, 0.f) * fmaxf(myb.w - myb.y, 0.f);
        svt[pos]   = (unsigned char)tid;
        if (axb == 0) g_vt[n * Tt + pos] = (unsigned char)tid;
    }
    if (tid == 0) {
        snv = __popc(smask[0]) + __popc(smask[1]);
        if (axb == 0) g_nvalid[n] = snv;
    }
    __syncthreads();
    int nv = snv;

    int a = axb * 256 + tid;
    float4 an = anchors[a];
    float a2 = fmaxf(an.z - an.x, 0.f) * fmaxf(an.w - an.y, 0.f);
    unsigned lane = tid & 31;
    int w = tid >> 5;

    float best = -1.0f; int arg = 0;
    for (int k = 0; k < nv; k++) {
        float4 b = sbox[k];
        float lx = fmaxf(b.x, an.x), ly = fmaxf(b.y, an.y);
        float rx = fminf(b.z, an.z), ry = fminf(b.w, an.w);
        float iw = fmaxf(rx - lx, 0.f), ih = fmaxf(ry - ly, 0.f);
        float inter = iw * ih;
        float uni = sarea[k] + a2 - inter;
        float iou = __fdividef(inter, fmaxf(uni, 1e-10f));  // approx div
        if (iou > best) { best = iou; arg = svt[k]; }       // first-max (smallest t)

        unsigned ib = __float_as_uint(iou);
        unsigned mx = __reduce_max_sync(0xFFFFFFFFu, ib);
        unsigned msk = __ballot_sync(0xFFFFFFFFu, ib == mx);
        if (lane == (unsigned)(__ffs(msk) - 1))
            swkey[w][k] = ((unsigned long long)mx << 32) |
                          (unsigned long long)(~(unsigned)a);
    }
    __syncthreads();

    int idx = n * Aa + a;
    int st = (best >= 0.5f) ? 2 : ((best < 0.4f) ? 1 : 0);
    g_asg[idx]   = arg;
    g_state[idx] = st;

    // warp-aggregated list appends
    {
        unsigned bpos = __ballot_sync(0xFFFFFFFFu, st == 2);
        unsigned bign = __ballot_sync(0xFFFFFFFFu, st == 0);
        unsigned lmask = (1u << lane) - 1u;
        int basep = 0, basei = 0;
        if (lane == 0) {
            if (bpos) {
                basep = atomicAdd(&g_npos, __popc(bpos));
                atomicAdd(&g_poscnt[n], __popc(bpos));
            }
            if (bign) basei = atomicAdd(&g_nign, __popc(bign));
        }
        basep = __shfl_sync(0xFFFFFFFFu, basep, 0);
        basei = __shfl_sync(0xFFFFFFFFu, basei, 0);
        if (st == 2) g_poslist[basep + __popc(bpos & lmask)] = idx;
        if (st == 0) g_ignlist[basei + __popc(bign & lmask)] = idx;
    }

    if (tid < nv) {
        unsigned long long m = swkey[0][tid];
        #pragma unroll
        for (int ww = 1; ww < 8; ww++) {
            unsigned long long o = swkey[ww][tid];
            if (o > m) m = o;
        }
        if ((m >> 32) != 0)
            atomicMax(&g_gtkey[n * Tt + tid], m);
    }

    // fused low-quality override: last finishing assignment block applies all
    __syncthreads();
    __threadfence();
    __shared__ bool slast;
    if (tid == 0)
        slast = (atomicAdd(&g_done1, 1u) == (unsigned)(AB - 1));
    __syncthreads();
    if (slast) {
        for (int idx2 = tid; idx2 < Nn * Tt; idx2 += 256) {
            int nn = idx2 >> 6, k = idx2 & 63;
            if (k < g_nvalid[nn]) {
                unsigned long long key = g_gtkey[nn * Tt + k];
                if ((key >> 32) != 0) {
                    int aa = (int)(~(unsigned)(key & 0xFFFFFFFFull));
                    int t = g_vt[nn * Tt + k];
                    int p = nn * Aa + aa;
                    atomicMax(&g_asg[p], 0x40000000 | t);
                    int old = atomicExch(&g_state[p], 2);
                    if (old != 2) {
                        int pp = atomicAdd(&g_npos, 1);
                        g_poslist[pp] = p | ((old == 0) ? IGN_FLAG : 0);
                        atomicAdd(&g_poscnt[nn], 1);
                    }
                }
            }
        }
        __syncthreads();
        __threadfence();
        if (tid == 0) atomicExch(&g_lqdone, 1u);   // release: lists final
    }
}

// ---------------- launch ----------------
extern "C" void kernel_launch(void* const* d_in, const int* in_sizes, int n_in,
                              void* d_out, int out_size) {
    const float*  y_true    = (const float*)d_in[0];
    const float*  bbox_true = (const float*)d_in[1];
    const float*  y_pred    = (const float*)d_in[2];
    const float4* bbox_pred = (const float4*)d_in[3];
    const float4* anchors   = (const float4*)d_in[4];
    float* out = (float*)d_out;

    kAll<<<TOTB, 256>>>(anchors, (const float4*)bbox_true, y_true,
                        (const float4*)y_pred, bbox_pred, bbox_true, out);
}

// round 16
// speedup vs baseline: 1.9961x; 1.0714x over previous
#include <cuda_runtime.h>
#include <math.h>

#define Nn 8
#define Tt 64
#define Aa 65536
#define Cc 80
#define NFLT4 (Aa * (Cc / 4))          // float4s of y_pred per image = 1,310,720
#define ITER 8
#define SBX_PER_N 640                   // stream blocks per image
#define SBb (SBX_PER_N * Nn)            // 5120 stream blocks
#define AB ((Aa / 256) * Nn)            // 2048 assignment blocks
#define CB 2048                         // correction blocks
#define TOTB (AB + SBb + CB + 1)        // + 1 final block

#define F_EPS 1e-6f
#define SL1_BETA (1.0f / 9.0f)
#define LN2 0.69314718055994531f
#define FOCAL_SCALE (0.75f * 0.69314718056f)   // 0.75 * ln2
#define IGN_FLAG (1 << 30)

// ---------------- scratch (device globals; no allocation) ----------------
__device__ int            g_state[Nn * Aa];   // 0=ignore 1=neg 2=pos
__device__ int            g_asg[Nn * Aa];     // bit30 = override, low bits = gt index t
__device__ int            g_nvalid[Nn];
__device__ unsigned char  g_vt[Nn * Tt];
__device__ unsigned char  g_label[Nn * Tt];
__device__ unsigned long long g_gtkey[Nn * Tt];
__device__ int            g_poscnt[Nn];
__device__ __align__(16) float g_pcls[SBb];
__device__ __align__(16) float g_qcls[CB];
__device__ __align__(16) float g_qbox[CB];
__device__ int            g_ignlist[Nn * Aa];
__device__ int            g_poslist[Nn * Aa];
__device__ int            g_nign;
__device__ int            g_npos;
__device__ unsigned       g_done1;    // assignment blocks completed
__device__ unsigned       g_lqdone;   // LQ tail complete (lists final)
__device__ unsigned       g_doneS;    // stream blocks completed
__device__ unsigned       g_doneC;    // correction blocks completed

// ---------------- helpers ----------------
__device__ __forceinline__ float rcp_approx(float x) {
    float r; asm("rcp.approx.f32 %0, %1;" : "=f"(r) : "f"(x)); return r;
}
__device__ __forceinline__ float ex2a(float x) {
    float r; asm("ex2.approx.f32 %0, %1;" : "=f"(r) : "f"(x)); return r;
}
__device__ __forceinline__ float lg2a(float x) {
    float r; asm("lg2.approx.f32 %0, %1;" : "=f"(r) : "f"(x)); return r;
}

// Sign-free focal kernel: returns p^2 * lg2(1+e^l).
// Full focal term = FOCAL_SCALE * focal_t(l) = 0.75 * p^2 * softplus(l).
// 12 SASS instr, 2 MUFU (EX2, LG2); reciprocal via bit-seed + 2 Newton (FMA pipe).
__device__ __forceinline__ float focal_t(float l) {
    float z = ex2a(l * 1.44269504f);                 // e^l
    float u = 1.0f + z;                              // (1, inf)
    float r = __int_as_float(0x7EF311C3 - __float_as_int(u));
    r = r * fmaf(-u, r, 2.0f);                       // Newton 1
    r = r * fmaf(-u, r, 2.0f);                       // Newton 2: rel err ~6e-6
    float zr = z * r;                                // p = sigmoid(l)
    return (zr * zr) * lg2a(u);                      // p^2 * lg2(1+e^l)
}

__device__ __forceinline__ void spin_ge(volatile unsigned* p, unsigned v) {
    while (*p < v) __nanosleep(200);
}

// ---------------- single fused launch; 32 regs for full occupancy ----------------
__global__ void __launch_bounds__(256, 8)
kAll(const float4* __restrict__ anchors,
     const float4* __restrict__ bb,
     const float* __restrict__ y_true,
     const float4* __restrict__ yp4,
     const float4* __restrict__ bbp4,
     const float* __restrict__ bbox_true,
     float* __restrict__ out) {
    int bid = blockIdx.x;
    int tid = threadIdx.x;

    // ================= STREAM BLOCKS =================
    if (bid >= AB && bid < AB + SBb) {
        int sb = bid - AB;
        int n = sb / SBX_PER_N;
        int bx = sb - n * SBX_PER_N;
        const float4* yp = yp4 + (size_t)n * NFLT4 + bx * (256 * ITER);
        float acc0 = 0.f, acc1 = 0.f;
        #pragma unroll
        for (int i = 0; i < ITER; i++) {
            float4 vv = yp[i * 256 + tid];
            acc0 += focal_t(vv.x) + focal_t(vv.z);
            acc1 += focal_t(vv.y) + focal_t(vv.w);
        }
        float clsl = acc0 + acc1;
        unsigned full = 0xFFFFFFFFu;
        #pragma unroll
        for (int o = 16; o > 0; o >>= 1)
            clsl += __shfl_down_sync(full, clsl, o);
        __shared__ float wc[8];
        int w = tid >> 5, lane = tid & 31;
        if (lane == 0) wc[w] = clsl;
        __syncthreads();
        if (tid == 0) {
            float c = 0.f;
            #pragma unroll
            for (int i = 0; i < 8; i++) c += wc[i];
            g_pcls[sb] = FOCAL_SCALE * c;
            __threadfence();
            atomicAdd(&g_doneS, 1u);
        }
        return;
    }

    // ================= CORRECTION BLOCKS =================
    if (bid >= AB + SBb && bid < AB + SBb + CB) {
        int cb = bid - AB - SBb;
        if (tid == 0) spin_ge(&g_lqdone, 1u);       // lists final after LQ tail
        __syncthreads();
        __threadfence();

        float cls = 0.f, box = 0.f;
        int gtid = cb * 256 + tid;
        const int stride = CB * 256;

        int nI = g_nign;
        int nItems = nI * 20;
        #pragma unroll 4
        for (int it = gtid; it < nItems; it += stride) {
            int e = it / 20;
            int qq = it - e * 20;
            int idx = g_ignlist[e];
            int n = idx >> 16;
            int a = idx & (Aa - 1);
            float4 vv = yp4[(size_t)n * NFLT4 + (size_t)a * 20 + qq];
            float S = focal_t(vv.x) + focal_t(vv.y) + focal_t(vv.z) + focal_t(vv.w);
            cls = fmaf(-FOCAL_SCALE, S, cls);
        }

        int nP = g_npos;
        for (int e = gtid; e < nP; e += stride) {
            int ent = g_poslist[e];
            int idx = ent & ~IGN_FLAG;
            int n = idx >> 16;
            int a = idx & (Aa - 1);
            const float4* yp = yp4 + (size_t)n * NFLT4 + (size_t)a * 20;

            if (ent & IGN_FLAG) {
                // was on the ignore list; its focal sum was subtracted above -> add back
                float S = 0.f;
                #pragma unroll 4
                for (int qq = 0; qq < 20; qq++) {
                    float4 vv = yp[qq];
                    S += focal_t(vv.x) + focal_t(vv.y) + focal_t(vv.z) + focal_t(vv.w);
                }
                cls = fmaf(FOCAL_SCALE, S, cls);
            }

            int v = g_asg[idx];
            int asg = (v & 0x40000000) ? (v & 0xFF) : v;
            int label = (int)g_label[n * Tt + asg];
            float4 vv = yp[label >> 2];
            int j = label & 3;
            float lsel = (j == 0) ? vv.x : ((j == 1) ? vv.y : ((j == 2) ? vv.z : vv.w));
            {
                // + alpha*q^2*softplus(-l)  (accurate path; rare)
                float mm = fabsf(lsel);
                float em = __expf(-mm);
                float uu = 1.0f + em;
                float r  = rcp_approx(uu);
                float lgv = __logf(uu);
                float p  = (lsel >= 0.f) ? r : em * r;
                float qd = 1.0f - p;
                float cep = lgv + fmaxf(-lsel, 0.f);
                // - stream's contribution for the label element (exact cancel)
                cls += 0.25f * qd * qd * cep - FOCAL_SCALE * focal_t(lsel);
            }
            float4 an = anchors[a];
            float4 bp = bbp4[idx];
            const float* bt = bbox_true + ((size_t)n * Tt + asg) * 4;
            float bx1 = bt[0], by1 = bt[1], bx2 = bt[2], by2 = bt[3];
            float wa = fmaxf(an.z - an.x, F_EPS);
            float ha = fmaxf(an.w - an.y, F_EPS);
            float cxa = an.x + 0.5f * wa;
            float cya = an.y + 0.5f * ha;
            float wt = fmaxf(bx2 - bx1, F_EPS);
            float ht = fmaxf(by2 - by1, F_EPS);
            float cxt = bx1 + 0.5f * (bx2 - bx1);
            float cyt = by1 + 0.5f * (by2 - by1);
            float tg0 = (cxt - cxa) / wa;
            float tg1 = (cyt - cya) / ha;
            float tg2 = logf(wt / wa);
            float tg3 = logf(ht / ha);
            float d0 = fabsf(tg0 - bp.x), d1 = fabsf(tg1 - bp.y);
            float d2 = fabsf(tg2 - bp.z), d3 = fabsf(tg3 - bp.w);
            box += (d0 < SL1_BETA) ? (0.5f * d0 * d0 / SL1_BETA) : (d0 - 0.5f * SL1_BETA);
            box += (d1 < SL1_BETA) ? (0.5f * d1 * d1 / SL1_BETA) : (d1 - 0.5f * SL1_BETA);
            box += (d2 < SL1_BETA) ? (0.5f * d2 * d2 / SL1_BETA) : (d2 - 0.5f * SL1_BETA);
            box += (d3 < SL1_BETA) ? (0.5f * d3 * d3 / SL1_BETA) : (d3 - 0.5f * SL1_BETA);
        }

        unsigned full = 0xFFFFFFFFu;
        #pragma unroll
        for (int o = 16; o > 0; o >>= 1) {
            cls += __shfl_down_sync(full, cls, o);
            box += __shfl_down_sync(full, box, o);
        }
        __shared__ float wc[8], wb[8];
        int w = tid >> 5, lane = tid & 31;
        if (lane == 0) { wc[w] = cls; wb[w] = box; }
        __syncthreads();
        if (tid == 0) {
            float c = 0.f, b = 0.f;
            #pragma unroll
            for (int i = 0; i < 8; i++) { c += wc[i]; b += wb[i]; }
            g_qcls[cb] = c;
            g_qbox[cb] = b;
            __threadfence();
            atomicAdd(&g_doneC, 1u);
        }
        return;
    }

    // ================= FINAL BLOCK =================
    if (bid == AB + SBb + CB) {
        if (tid == 0) {
            spin_ge(&g_doneS, (unsigned)SBb);
            spin_ge(&g_doneC, (unsigned)CB);
        }
        __syncthreads();
        __threadfence();

        __shared__ double sc[256], sb2[256];
        double c = 0.0, b = 0.0;
        {
            const float4* pc4 = (const float4*)g_pcls;     // 1280
            #pragma unroll 5
            for (int i = tid; i < SBb / 4; i += 256) {
                float4 v = pc4[i];
                c += (double)((v.x + v.y) + (v.z + v.w));
            }
            const float4* qc4 = (const float4*)g_qcls;     // 512
            const float4* qb4 = (const float4*)g_qbox;
            #pragma unroll 2
            for (int i = tid; i < CB / 4; i += 256) {
                float4 v = qc4[i];
                float4 u = qb4[i];
                c += (double)((v.x + v.y) + (v.z + v.w));
                b += (double)((u.x + u.y) + (u.z + u.w));
            }
        }
        sc[tid] = c; sb2[tid] = b;
        __syncthreads();
        for (int s = 128; s > 0; s >>= 1) {
            if (tid < s) { sc[tid] += sc[tid + s]; sb2[tid] += sb2[tid + s]; }
            __syncthreads();
        }
        if (tid == 0) {
            double avg = 0.0;
            for (int nn = 0; nn < Nn; nn++) {
                double p = (double)g_poscnt[nn];
                avg += (p > 1.0) ? p : 1.0;
            }
            float clsO = (float)(sc[0] / avg);
            float boxO = (float)(sb2[0] / avg);
            if (isnan(clsO) || isinf(clsO)) clsO = 0.f;
            if (isnan(boxO) || isinf(boxO)) boxO = 0.f;
            out[0] = clsO;
            out[1] = boxO;
        }
        __syncthreads();
        // resets for next graph replay
        if (tid == 0) {
            g_done1 = 0; g_lqdone = 0; g_doneS = 0; g_doneC = 0;
            g_npos = 0; g_nign = 0;
        }
        if (tid < Nn) g_poscnt[tid] = 0;
        for (int i = tid; i < Nn * Tt; i += 256) g_gtkey[i] = 0ull;
        return;
    }

    // ================= ASSIGNMENT BLOCKS (bid < AB) =================
    int n = bid >> 8;
    int axb = bid & 255;

    __shared__ float4 sbox[Tt];
    __shared__ float  sarea[Tt];
    __shared__ unsigned char svt[Tt];
    __shared__ unsigned long long swkey[8][Tt];
    __shared__ unsigned smask[2];
    __shared__ int snv;

    float4 myb; bool myvalid = false; unsigned mk = 0;
    if (tid < 64) {
        myb = bb[n * Tt + tid];
        myvalid = (myb.x > 0.f) || (myb.y > 0.f) || (myb.z > 0.f) || (myb.w > 0.f);
        mk = __ballot_sync(0xFFFFFFFFu, myvalid);
        if ((tid & 31) == 0) smask[tid >> 5] = mk;
    }
    if (axb == 0 && tid >= 64 && tid < 128) {
        int r = n * Tt + (tid - 64);
        const float4* row = (const float4*)(y_true + (size_t)r * Cc);
        int lab = 0;
        #pragma unroll 4
        for (int qq = 0; qq < Cc / 4; qq++) {
            float4 v = row[qq];
            if (v.x > 0.5f) lab = 4 * qq;
            if (v.y > 0.5f) lab = 4 * qq + 1;
            if (v.z > 0.5f) lab = 4 * qq + 2;
            if (v.w > 0.5f) lab = 4 * qq + 3;
        }
        g_label[r] = (unsigned char)lab;
    }
    __syncthreads();
    if (tid < 64 && myvalid) {
        int pos = __popc(mk & ((1u << (tid & 31)) - 1)) +
                  ((tid >= 32) ? __popc(smask[0]) : 0);
        sbox[pos]  = myb;
        sarea[pos] = fmaxf(myb.z - myb.x, 0.f) * fmaxf(myb.w - myb.y, 0.f);
        svt[pos]   = (unsigned char)tid;
        if (axb == 0) g_vt[n * Tt + pos] = (unsigned char)tid;
    }
    if (tid == 0) {
        snv = __popc(smask[0]) + __popc(smask[1]);
        if (axb == 0) g_nvalid[n] = snv;
    }
    __syncthreads();
    int nv = snv;

    int a = axb * 256 + tid;
    float4 an = anchors[a];
    float a2 = fmaxf(an.z - an.x, 0.f) * fmaxf(an.w - an.y, 0.f);
    unsigned lane = tid & 31;
    int w = tid >> 5;

    float best = -1.0f; int arg = 0;
    for (int k = 0; k < nv; k++) {
        float4 b = sbox[k];
        float lx = fmaxf(b.x, an.x), ly = fmaxf(b.y, an.y);
        float rx = fminf(b.z, an.z), ry = fminf(b.w, an.w);
        float iw = fmaxf(rx - lx, 0.f), ih = fmaxf(ry - ly, 0.f);
        float inter = iw * ih;
        float uni = sarea[k] + a2 - inter;
        float iou = __fdividef(inter, fmaxf(uni, 1e-10f));  // approx div
        if (iou > best) { best = iou; arg = svt[k]; }       // first-max (smallest t)

        unsigned ib = __float_as_uint(iou);
        unsigned mx = __reduce_max_sync(0xFFFFFFFFu, ib);
        unsigned msk = __ballot_sync(0xFFFFFFFFu, ib == mx);
        if (lane == (unsigned)(__ffs(msk) - 1))
            swkey[w][k] = ((unsigned long long)mx << 32) |
                          (unsigned long long)(~(unsigned)a);
    }
    __syncthreads();

    int idx = n * Aa + a;
    int st = (best >= 0.5f) ? 2 : ((best < 0.4f) ? 1 : 0);
    g_asg[idx]   = arg;
    g_state[idx] = st;

    // warp-aggregated list appends
    {
        unsigned bpos = __ballot_sync(0xFFFFFFFFu, st == 2);
        unsigned bign = __ballot_sync(0xFFFFFFFFu, st == 0);
        unsigned lmask = (1u << lane) - 1u;
        int basep = 0, basei = 0;
        if (lane == 0) {
            if (bpos) {
                basep = atomicAdd(&g_npos, __popc(bpos));
                atomicAdd(&g_poscnt[n], __popc(bpos));
            }
            if (bign) basei = atomicAdd(&g_nign, __popc(bign));
        }
        basep = __shfl_sync(0xFFFFFFFFu, basep, 0);
        basei = __shfl_sync(0xFFFFFFFFu, basei, 0);
        if (st == 2) g_poslist[basep + __popc(bpos & lmask)] = idx;
        if (st == 0) g_ignlist[basei + __popc(bign & lmask)] = idx;
    }

    if (tid < nv) {
        unsigned long long m = swkey[0][tid];
        #pragma unroll
        for (int ww = 1; ww < 8; ww++) {
            unsigned long long o = swkey[ww][tid];
            if (o > m) m = o;
        }
        if ((m >> 32) != 0)
            atomicMax(&g_gtkey[n * Tt + tid], m);
    }

    // fused low-quality override: last finishing assignment block applies all
    __syncthreads();
    __threadfence();
    __shared__ bool slast;
    if (tid == 0)
        slast = (atomicAdd(&g_done1, 1u) == (unsigned)(AB - 1));
    __syncthreads();
    if (slast) {
        for (int idx2 = tid; idx2 < Nn * Tt; idx2 += 256) {
            int nn = idx2 >> 6, k = idx2 & 63;
            if (k < g_nvalid[nn]) {
                unsigned long long key = g_gtkey[nn * Tt + k];
                if ((key >> 32) != 0) {
                    int aa = (int)(~(unsigned)(key & 0xFFFFFFFFull));
                    int t = g_vt[nn * Tt + k];
                    int p = nn * Aa + aa;
                    atomicMax(&g_asg[p], 0x40000000 | t);
                    int old = atomicExch(&g_state[p], 2);
                    if (old != 2) {
                        int pp = atomicAdd(&g_npos, 1);
                        g_poslist[pp] = p | ((old == 0) ? IGN_FLAG : 0);
                        atomicAdd(&g_poscnt[nn], 1);
                    }
                }
            }
        }
        __syncthreads();
        __threadfence();
        if (tid == 0) atomicExch(&g_lqdone, 1u);   // release: lists final
    }
}

// ---------------- launch ----------------
extern "C" void kernel_launch(void* const* d_in, const int* in_sizes, int n_in,
                              void* d_out, int out_size) {
    const float*  y_true    = (const float*)d_in[0];
    const float*  bbox_true = (const float*)d_in[1];
    const float*  y_pred    = (const float*)d_in[2];
    const float4* bbox_pred = (const float4*)d_in[3];
    const float4* anchors   = (const float4*)d_in[4];
    float* out = (float*)d_out;

    kAll<<<TOTB, 256>>>(anchors, (const float4*)bbox_true, y_true,
                        (const float4*)y_pred, bbox_pred, bbox_true, out);
}